// round 15
// baseline (speedup 1.0000x reference)
#include <cuda_runtime.h>
#include <cuda_bf16.h>
#include <math.h>

#define NBATCH 32
#define NNODE  512
#define NHEAD  8
#define FHID   16

// ---------------- scratch (device globals; no allocations) ----------------
__device__ float    g_hp1[NBATCH*NHEAD*NNODE*FHID];   // 8 MB
__device__ float    g_as [NBATCH*NHEAD*NNODE];
__device__ float    g_Es [NBATCH*NHEAD*NNODE];
__device__ float    g_Fs [NBATCH*NHEAD*NNODE];
__device__ float    g_ad [NBATCH*NHEAD*NNODE];
__device__ float    g_Ed [NBATCH*NHEAD*NNODE];
__device__ float    g_Fd [NBATCH*NHEAD*NNODE];
__device__ float    g_inv[NBATCH*NHEAD*NNODE];        // per-row 1/sum
__device__ unsigned g_bits[NBATCH*NNODE*16];          // 1 MB bit-packed adjacency
__device__ float    g_x  [NBATCH*NNODE*128];          // 8 MB layer-2 input
__device__ float    g_hp2[NBATCH*NNODE*64];           // 4 MB
__device__ float    g_as2[NBATCH*NNODE];
__device__ float    g_ad2[NBATCH*NNODE];

// ---------------- packed f32x2 helpers (sm_103a) ----------------
static __device__ __forceinline__ unsigned long long pk2(float lo, float hi) {
    unsigned long long r;
    asm("mov.b64 %0,{%1,%2};" : "=l"(r) : "f"(lo), "f"(hi));
    return r;
}
static __device__ __forceinline__ void upk2(unsigned long long v, float& lo, float& hi) {
    asm("mov.b64 {%0,%1},%2;" : "=f"(lo), "=f"(hi) : "l"(v));
}
static __device__ __forceinline__ unsigned long long fma2(unsigned long long a,
                                                          unsigned long long b,
                                                          unsigned long long c) {
    unsigned long long d;
    asm("fma.rn.f32x2 %0,%1,%2,%3;" : "=l"(d) : "l"(a), "l"(b), "l"(c));
    return d;
}
static __device__ __forceinline__ unsigned long long add2(unsigned long long a,
                                                          unsigned long long b) {
    unsigned long long d;
    asm("add.rn.f32x2 %0,%1,%2;" : "=l"(d) : "l"(a), "l"(b));
    return d;
}

// ---------------- K0: bit-pack adjacency ----------------
__global__ void k_pack(const int* __restrict__ adj) {
    int idx = blockIdx.x * 256 + threadIdx.x;
    unsigned m = __ballot_sync(0xffffffffu, adj[idx] > 0);
    if ((threadIdx.x & 31) == 0) g_bits[idx >> 5] = m;
}

// ---------------- K1: layer-1 projection + tanh + exp tables ----------------
// grid (8, 2, 32), block 512; warp-per-node, lane owns output pair
__global__ void __launch_bounds__(512) k_proj1(
    const float* __restrict__ features, const float* __restrict__ line_emb,
    const int*   __restrict__ v_types,  const float* __restrict__ w1,
    const float* __restrict__ a_src1,   const float* __restrict__ a_dst1)
{
    extern __shared__ float sm1[];
    float* ws   = sm1;             // 12288: [t][f][l64]
    float* xv   = ws + 12288;      // 4096: 64 nodes x 64
    float* asr  = xv + 4096;       // 64
    float* ads  = asr + 64;        // 64
    int*   vt   = (int*)(ads + 64);// 64
    int tid = threadIdx.x;
    int bx = blockIdx.x, hh = blockIdx.y, b = blockIdx.z;
    int nbase = bx * 64;

    for (int i = tid; i < 12288; i += 512) {
        int l64 = i & 63, f = (i >> 6) & 63, t = i >> 12;
        int h = hh * 4 + (l64 >> 4), o = l64 & 15;
        ws[i] = w1[((t * 8 + h) * 64 + f) * 16 + o];
    }
    for (int i = tid; i < 4096; i += 512) {
        int node = i >> 6, f = i & 63;
        int n = nbase + node;
        xv[i] = (f < 32) ? features[(b * NNODE + n) * 32 + f]
                         : line_emb[(b * NNODE + n) * 32 + f - 32];
    }
    if (tid < 64) {
        int h = hh * 4 + (tid >> 4), o = tid & 15;
        asr[tid] = a_src1[h * 16 + o];
        ads[tid] = a_dst1[h * 16 + o];
        vt[tid] = v_types[b * NNODE + nbase + tid];
    }
    __syncthreads();

    int lane = tid & 31, w = tid >> 5;
    int gh = hh * 4 + (lane >> 3);
    float a0v = asr[2 * lane], a1v = asr[2 * lane + 1];
    float d0v = ads[2 * lane], d1v = ads[2 * lane + 1];
    unsigned long long z = pk2(0.f, 0.f);

    #pragma unroll
    for (int r = 0; r < 4; r++) {
        int nloc = w * 4 + r;
        int n = nbase + nloc;
        int ty = vt[nloc];
        const float* wp = ws + ty * 4096 + 2 * lane;
        const float* xp = xv + nloc * 64;
        unsigned long long acc0 = z, acc1 = z;
        #pragma unroll
        for (int f = 0; f < 64; f += 2) {
            float2 x2 = *(const float2*)&xp[f];
            unsigned long long w0 = *(const unsigned long long*)&wp[f * 64];
            unsigned long long w1v = *(const unsigned long long*)&wp[(f + 1) * 64];
            acc0 = fma2(pk2(x2.x, x2.x), w0, acc0);
            acc1 = fma2(pk2(x2.y, x2.y), w1v, acc1);
        }
        float v0, v1;
        upk2(add2(acc0, acc1), v0, v1);
        int o = (2 * lane) & 15;
        *(float2*)&g_hp1[((b * NHEAD + gh) * NNODE + n) * FHID + o] =
            make_float2(v0, v1);
        float th0 = tanhf(v0), th1 = tanhf(v1);
        float ps = th0 * a0v + th1 * a1v;
        float pd = th0 * d0v + th1 * d1v;
        #pragma unroll
        for (int off = 4; off; off >>= 1) {
            ps += __shfl_xor_sync(0xffffffffu, ps, off);
            pd += __shfl_xor_sync(0xffffffffu, pd, off);
        }
        if ((lane & 7) == 0) {
            int ai = (b * NHEAD + gh) * NNODE + n;
            g_as[ai] = ps; g_Es[ai] = expf(ps); g_Fs[ai] = expf(0.2f * ps);
            g_ad[ai] = pd; g_Ed[ai] = expf(pd); g_Fd[ai] = expf(0.2f * pd);
        }
    }
}

// ---------------- K2a: attn numerators + row sums + COALESCED attn1 store ----------------
// grid (2, 8, 32) = (nhalf, h, b), 256 threads = 8 warps, warp-per-row (32 rows each).
__global__ void __launch_bounds__(256) k_store(float* __restrict__ attn_out) {
    __shared__ float4   rc_s[256];        // (as, Es, Fs, 0) for block's rows
    __shared__ float4   tbl_s[512];       // (ad, Ed, Fd, 0) all columns
    __shared__ unsigned bits_s[256 * 16]; // [row][w]
    int tid = threadIdx.x;
    int nh = blockIdx.x, h = blockIdx.y, b = blockIdx.z;
    int bh = b * NHEAD + h;
    int n0 = nh * 256;

    for (int i = tid; i < 256; i += 256)
        rc_s[i] = make_float4(g_as[bh * 512 + n0 + i], g_Es[bh * 512 + n0 + i],
                              g_Fs[bh * 512 + n0 + i], 0.f);
    for (int i = tid; i < 512; i += 256)
        tbl_s[i] = make_float4(g_ad[bh * 512 + i], g_Ed[bh * 512 + i],
                               g_Fd[bh * 512 + i], 0.f);
    for (int i = tid; i < 4096; i += 256)
        bits_s[i] = g_bits[b * 8192 + n0 * 16 + i];
    __syncthreads();

    int lane = tid & 31, w = tid >> 5;
    float ad[16], Ed[16], Fd[16];
    #pragma unroll
    for (int k = 0; k < 4; k++)
        #pragma unroll
        for (int c = 0; c < 4; c++) {
            float4 t = tbl_s[4 * lane + c + 128 * k];
            ad[4 * k + c] = t.x; Ed[4 * k + c] = t.y; Fd[4 * k + c] = t.z;
        }
    unsigned mask[4];
    #pragma unroll
    for (int c = 0; c < 4; c++) mask[c] = 1u << (((lane & 7) * 4) + c);
    int wbase = lane >> 3;

    float* obase = attn_out + (size_t)bh * 512 * 512;
    for (int r = 0; r < 32; r++) {
        int lrow = w * 32 + r;
        int grow = n0 + lrow;
        float4 rc = rc_s[lrow];
        float nb[16];
        float sum = 0.f;
        #pragma unroll
        for (int k = 0; k < 4; k++) {
            unsigned wa = bits_s[lrow * 16 + wbase + 4 * k];
            #pragma unroll
            for (int c = 0; c < 4; c++) {
                int i = 4 * k + c;
                float sa = rc.x + ad[i];
                float t  = (sa >= 0.f) ? Ed[i] : Fd[i];
                float cc = (sa >= 0.f) ? rc.y : rc.z;
                float n  = (wa & mask[c]) ? t * cc : 0.f;
                nb[i] = n;
                sum += n;
            }
        }
        #pragma unroll
        for (int off = 16; off; off >>= 1)
            sum += __shfl_xor_sync(0xffffffffu, sum, off);
        float inva = 1.f / sum;
        if (lane == 0) g_inv[bh * 512 + grow] = inva;
        float* rp = obase + (size_t)grow * 512 + 4 * lane;
        #pragma unroll
        for (int k = 0; k < 4; k++)
            __stcs((float4*)(rp + 128 * k),
                   make_float4(nb[4*k] * inva, nb[4*k+1] * inva,
                               nb[4*k+2] * inva, nb[4*k+3] * inva));
    }
}

// ---------------- K2b: out1 GEMM, 2 rows/thread (attn recomputed, no stores) ----------------
// grid (2, 8, 32) = (nhalf, h, b), 128 threads, rows n0+2t/n0+2t+1
// dyn smem 57408 B -> 4 blocks/SM = 16 warps, 512 blocks (3.46/SM, balanced)
__global__ void __launch_bounds__(128) k_gemm(const float* __restrict__ b1) {
    extern __shared__ float smf[];
    float*    hp_s   = smf;                       // 8192 floats [m][o]
    float4*   tbl    = (float4*)(smf + 8192);     // 512 float4 (ad, Ed, Fd, 0)
    unsigned* bits_s = (unsigned*)(smf + 10240);  // 4096 words, layout [w][r], 256 rows
    float*    b1s    = smf + 14336;               // 16
    int tid = threadIdx.x;
    int nh = blockIdx.x, h = blockIdx.y, b = blockIdx.z;
    int bh = b * NHEAD + h;
    int n0 = nh * 256;

    for (int i = tid; i < 8192; i += 128) hp_s[i] = g_hp1[bh * 8192 + i];
    for (int i = tid; i < 512; i += 128)
        tbl[i] = make_float4(g_ad[bh * 512 + i], g_Ed[bh * 512 + i],
                             g_Fd[bh * 512 + i], 0.f);
    for (int i = tid; i < 4096; i += 128) {
        int w = i >> 8, r = i & 255;
        bits_s[i] = g_bits[b * 8192 + (n0 + r) * 16 + w];
    }
    if (tid < 16) b1s[tid] = b1[tid];

    int rla = 2 * tid, rlb = rla + 1;
    int na = n0 + rla, nb = n0 + rlb;
    float as_a = g_as[bh * 512 + na], as_b = g_as[bh * 512 + nb];
    float iva = g_inv[bh * 512 + na], ivb = g_inv[bh * 512 + nb];
    float Esa = g_Es[bh * 512 + na] * iva, Fsa = g_Fs[bh * 512 + na] * iva;
    float Esb = g_Es[bh * 512 + nb] * ivb, Fsb = g_Fs[bh * 512 + nb] * ivb;
    __syncthreads();

    unsigned long long acc[16];
    unsigned long long z = pk2(0.f, 0.f);
    #pragma unroll
    for (int q = 0; q < 16; q++) acc[q] = z;

    for (int mw = 0; mw < 16; mw++) {
        unsigned wa = bits_s[mw * 256 + rla];
        unsigned wb = bits_s[mw * 256 + rlb];
        #pragma unroll
        for (int mi = 0; mi < 32; mi++) {
            int m = mw * 32 + mi;
            float4 t = tbl[m];
            float sa = as_a + t.x, sb = as_b + t.x;
            float ca = (sa >= 0.f) ? Esa : Fsa;
            float cb = (sb >= 0.f) ? Esb : Fsb;
            if (!((wa >> mi) & 1u)) ca = 0.f;
            if (!((wb >> mi) & 1u)) cb = 0.f;
            float ea = ca * ((sa >= 0.f) ? t.y : t.z);
            float eb = cb * ((sb >= 0.f) ? t.y : t.z);
            unsigned long long pa = pk2(ea, ea);
            unsigned long long pb = pk2(eb, eb);
            const unsigned long long* hq =
                (const unsigned long long*)(hp_s + m * 16);
            #pragma unroll
            for (int q = 0; q < 8; q++) {
                acc[q]     = fma2(pa, hq[q], acc[q]);
                acc[8 + q] = fma2(pb, hq[q], acc[8 + q]);
            }
        }
    }

    float va[16], vb[16];
    #pragma unroll
    for (int q = 0; q < 8; q++) {
        upk2(acc[q],     va[2 * q], va[2 * q + 1]);
        upk2(acc[8 + q], vb[2 * q], vb[2 * q + 1]);
    }
    float ra[16], rb[16];
    #pragma unroll
    for (int k = 0; k < 16; k++) {
        float xa = va[k] + b1s[k];
        float xb = vb[k] + b1s[k];
        ra[k] = xa > 0.f ? xa : expm1f(xa);
        rb[k] = xb > 0.f ? xb : expm1f(xb);
    }
    float* da = &g_x[(size_t)(b * 512 + na) * 128 + h * 16];
    float* db = &g_x[(size_t)(b * 512 + nb) * 128 + h * 16];
    #pragma unroll
    for (int q = 0; q < 4; q++) {
        ((float4*)da)[q] = make_float4(ra[4*q], ra[4*q+1], ra[4*q+2], ra[4*q+3]);
        ((float4*)db)[q] = make_float4(rb[4*q], rb[4*q+1], rb[4*q+2], rb[4*q+3]);
    }
}

// ---------------- K3: layer-2 projection; LDG.128 weights, quad-per-lane ----------------
__global__ void __launch_bounds__(256, 2) k_proj2(
    const int* __restrict__ v_types, const float* __restrict__ w2,
    const float* __restrict__ a_src2, const float* __restrict__ a_dst2)
{
    __shared__ float xv[32 * 128];
    __shared__ float asw[64], adw[64];
    __shared__ int   vt[32];
    int tid = threadIdx.x, b = blockIdx.y, bx = blockIdx.x;
    int nbase = bx * 32;

    for (int i = tid; i < 4096; i += 256)
        xv[i] = g_x[(size_t)(b * 512 + nbase) * 128 + i];
    if (tid < 64) { asw[tid] = a_src2[tid]; adw[tid] = a_dst2[tid]; }
    if (tid < 32) vt[tid] = v_types[b * 512 + nbase + tid];
    __syncthreads();

    int lane = tid & 31, w = tid >> 5;
    int half = lane >> 4, l16 = lane & 15;
    int o = l16 * 4;
    float a0v = asw[o], a1v = asw[o + 1], a2v = asw[o + 2], a3v = asw[o + 3];
    float d0v = adw[o], d1v = adw[o + 1], d2v = adw[o + 2], d3v = adw[o + 3];
    unsigned long long z = pk2(0.f, 0.f);

    #pragma unroll
    for (int pass = 0; pass < 2; pass++) {
        int nloc = pass * 16 + w * 2 + half;
        int n = nbase + nloc;
        int ty = vt[nloc];
        const float4* wp = (const float4*)(w2 + ty * 8192 + o);
        const float* xp = xv + nloc * 128;
        unsigned long long acc01 = z, acc23 = z;
        #pragma unroll
        for (int c = 0; c < 16; c++) {
            float4 wb[8];
            #pragma unroll
            for (int j = 0; j < 8; j++)
                wb[j] = __ldg(wp + (c * 8 + j) * 16);
            float4 xa = *(const float4*)&xp[c * 8];
            float4 xc = *(const float4*)&xp[c * 8 + 4];
            float xs[8] = {xa.x, xa.y, xa.z, xa.w, xc.x, xc.y, xc.z, xc.w};
            #pragma unroll
            for (int j = 0; j < 8; j++) {
                unsigned long long xx = pk2(xs[j], xs[j]);
                acc01 = fma2(xx, pk2(wb[j].x, wb[j].y), acc01);
                acc23 = fma2(xx, pk2(wb[j].z, wb[j].w), acc23);
            }
        }
        float v0, v1, v2, v3;
        upk2(acc01, v0, v1);
        upk2(acc23, v2, v3);
        *(float4*)&g_hp2[(size_t)(b * 512 + n) * 64 + o] =
            make_float4(v0, v1, v2, v3);
        float th0 = tanhf(v0), th1 = tanhf(v1), th2 = tanhf(v2), th3 = tanhf(v3);
        float ps = th0 * a0v + th1 * a1v + th2 * a2v + th3 * a3v;
        float pd = th0 * d0v + th1 * d1v + th2 * d2v + th3 * d3v;
        #pragma unroll
        for (int off = 8; off; off >>= 1) {
            ps += __shfl_xor_sync(0xffffffffu, ps, off);
            pd += __shfl_xor_sync(0xffffffffu, pd, off);
        }
        if (l16 == 0) {
            g_as2[b * 512 + n] = ps;
            g_ad2[b * 512 + n] = pd;
        }
    }
}

// ---------------- K4: layer-2 rows 0/1 + MLP + log_softmax ----------------
__global__ void __launch_bounds__(512) k_final(
    const float* __restrict__ b2,
    const float* __restrict__ fc1_w, const float* __restrict__ fc1_b,
    const float* __restrict__ fc2_w, const float* __restrict__ fc2_b,
    const float* __restrict__ fc3_w, const float* __restrict__ fc3_b,
    float* __restrict__ out_scores, float* __restrict__ out_vsm)
{
    __shared__ float att2[2 * 512];
    __shared__ float inv[2];
    __shared__ float part[512];
    __shared__ float xrow[128];
    __shared__ float vsm[64], v1[192], v2s[64];
    __shared__ float red[32];
    __shared__ float sc[2];
    int tid = threadIdx.x, b = blockIdx.x;
    int lane = tid & 31, wid = tid >> 5;

    float ad2 = g_ad2[b * 512 + tid];
    unsigned wrd  = g_bits[b * 8192 + (tid >> 5)];
    unsigned wrd1 = g_bits[b * 8192 + 16 + (tid >> 5)];
    float as0 = g_as2[b * 512 + 0], as1 = g_as2[b * 512 + 1];
    float s0 = as0 + ad2, s1 = as1 + ad2;
    float e0 = ((wrd  >> lane) & 1u) ? expf(s0 >= 0.f ? s0 : 0.2f * s0) : 0.f;
    float e1 = ((wrd1 >> lane) & 1u) ? expf(s1 >= 0.f ? s1 : 0.2f * s1) : 0.f;
    att2[tid] = e0;
    att2[512 + tid] = e1;
    float p0 = e0, p1 = e1;
    #pragma unroll
    for (int off = 16; off; off >>= 1) {
        p0 += __shfl_xor_sync(0xffffffffu, p0, off);
        p1 += __shfl_xor_sync(0xffffffffu, p1, off);
    }
    if (lane == 0) { red[wid] = p0; red[16 + wid] = p1; }
    __syncthreads();
    if (tid < 32) {
        float v = red[tid];
        #pragma unroll
        for (int off = 8; off; off >>= 1)
            v += __shfl_xor_sync(0xffffffffu, v, off);
        if (tid == 0)  inv[0] = 1.f / v;
        if (tid == 16) inv[1] = 1.f / v;
    }
    __syncthreads();

    {
        int r = tid >> 8, o = tid & 63, sub = (tid >> 6) & 3;
        const float* hp = g_hp2 + (size_t)b * 32768 + o;
        const float* av = att2 + r * 512 + sub * 128;
        float a0 = 0.f, a1 = 0.f, a2 = 0.f, a3 = 0.f;
        int mb = sub * 128;
        #pragma unroll 4
        for (int k = 0; k < 128; k += 4) {
            a0 = fmaf(av[k],     hp[(size_t)(mb + k) * 64],     a0);
            a1 = fmaf(av[k + 1], hp[(size_t)(mb + k + 1) * 64], a1);
            a2 = fmaf(av[k + 2], hp[(size_t)(mb + k + 2) * 64], a2);
            a3 = fmaf(av[k + 3], hp[(size_t)(mb + k + 3) * 64], a3);
        }
        part[tid] = (a0 + a1) + (a2 + a3);
    }
    __syncthreads();
    if (tid < 128) {
        int r = tid >> 6, o = tid & 63;
        float x = (part[r * 256 + o] + part[r * 256 + 64 + o] +
                   part[r * 256 + 128 + o] + part[r * 256 + 192 + o]) * inv[r] + b2[o];
        xrow[tid] = x > 0.f ? x : expm1f(x);
    }
    __syncthreads();
    if (tid < 64) {
        float vv = xrow[tid] * xrow[64 + tid];
        vsm[tid] = vv;
        out_vsm[b * 64 + tid] = vv;
    }
    __syncthreads();
    if (tid < 192) {
        float acc = fc1_b[tid];
        for (int f = 0; f < 64; f++) acc = fmaf(vsm[f], fc1_w[f * 192 + tid], acc);
        v1[tid] = fmaxf(acc, 0.f);
    }
    __syncthreads();
    if (tid < 64) {
        float acc = fc2_b[tid];
        for (int f = 0; f < 192; f++) acc = fmaf(v1[f], fc2_w[f * 64 + tid], acc);
        v2s[tid] = fmaxf(acc, 0.f);
    }
    __syncthreads();
    if (tid < 2) {
        float acc = fc3_b[tid];
        for (int f = 0; f < 64; f++) acc = fmaf(v2s[f], fc3_w[f * 2 + tid], acc);
        sc[tid] = acc;
    }
    __syncthreads();
    if (tid < 2) {
        float m = fmaxf(sc[0], sc[1]);
        float lse = m + logf(expf(sc[0] - m) + expf(sc[1] - m));
        out_scores[b * 2 + tid] = sc[tid] - lse;
    }
}

// ---------------- launch ----------------
extern "C" void kernel_launch(void* const* d_in, const int* in_sizes, int n_in,
                              void* d_out, int out_size) {
    (void)in_sizes; (void)n_in; (void)out_size;
    const float* features = (const float*)d_in[0];
    const int*   adj      = (const int*)  d_in[1];
    const float* line_emb = (const float*)d_in[5];
    const int*   v_types  = (const int*)  d_in[6];
    const float* w1       = (const float*)d_in[7];
    const float* a_src1   = (const float*)d_in[8];
    const float* a_dst1   = (const float*)d_in[9];
    const float* b1       = (const float*)d_in[10];
    const float* w2       = (const float*)d_in[11];
    const float* a_src2   = (const float*)d_in[12];
    const float* a_dst2   = (const float*)d_in[13];
    const float* b2       = (const float*)d_in[14];
    const float* fc1_w    = (const float*)d_in[15];
    const float* fc1_b    = (const float*)d_in[16];
    const float* fc2_w    = (const float*)d_in[17];
    const float* fc2_b    = (const float*)d_in[18];
    const float* fc3_w    = (const float*)d_in[19];
    const float* fc3_b    = (const float*)d_in[20];

    float* out   = (float*)d_out;
    float* vsm   = out + 64;       // v_sim_mul [32,64]
    float* attn1 = out + 2112;     // attn1 [32,8,512,512]

    cudaFuncSetAttribute(k_proj1, cudaFuncAttributeMaxDynamicSharedMemorySize, 67000);
    cudaFuncSetAttribute(k_gemm,  cudaFuncAttributeMaxDynamicSharedMemorySize, 58000);

    k_pack <<<32768, 256>>>(adj);
    k_proj1<<<dim3(8, 2, 32), 512, 66304>>>(features, line_emb, v_types, w1, a_src1, a_dst1);
    k_store<<<dim3(2, 8, 32), 256>>>(attn1);
    k_gemm <<<dim3(2, 8, 32), 128, 57408>>>(b1);
    k_proj2<<<dim3(16, 32), 256>>>(v_types, w2, a_src2, a_dst2);
    k_final<<<32, 512>>>(b2, fc1_w, fc1_b, fc2_w, fc2_b, fc3_w, fc3_b, out, vsm);
}

// round 16
// speedup vs baseline: 1.0354x; 1.0354x over previous
#include <cuda_runtime.h>
#include <cuda_bf16.h>
#include <math.h>

#define NBATCH 32
#define NNODE  512
#define NHEAD  8
#define FHID   16

// ---------------- scratch (device globals; no allocations) ----------------
__device__ float    g_hp1[NBATCH*NHEAD*NNODE*FHID];   // 8 MB
__device__ float    g_as [NBATCH*NHEAD*NNODE];
__device__ float    g_Es [NBATCH*NHEAD*NNODE];
__device__ float    g_Fs [NBATCH*NHEAD*NNODE];
__device__ float    g_ad [NBATCH*NHEAD*NNODE];
__device__ float    g_Ed [NBATCH*NHEAD*NNODE];
__device__ float    g_Fd [NBATCH*NHEAD*NNODE];
__device__ float    g_inv[NBATCH*NHEAD*NNODE];        // per-row 1/sum
__device__ unsigned g_bits[NBATCH*NNODE*16];          // 1 MB bit-packed adjacency
__device__ float    g_x  [NBATCH*NNODE*128];          // 8 MB layer-2 input
__device__ float    g_hp2[NBATCH*NNODE*64];           // 4 MB
__device__ float    g_as2[NBATCH*NNODE];
__device__ float    g_ad2[NBATCH*NNODE];

// ---------------- packed f32x2 helpers (sm_103a) ----------------
static __device__ __forceinline__ unsigned long long pk2(float lo, float hi) {
    unsigned long long r;
    asm("mov.b64 %0,{%1,%2};" : "=l"(r) : "f"(lo), "f"(hi));
    return r;
}
static __device__ __forceinline__ void upk2(unsigned long long v, float& lo, float& hi) {
    asm("mov.b64 {%0,%1},%2;" : "=f"(lo), "=f"(hi) : "l"(v));
}
static __device__ __forceinline__ unsigned long long fma2(unsigned long long a,
                                                          unsigned long long b,
                                                          unsigned long long c) {
    unsigned long long d;
    asm("fma.rn.f32x2 %0,%1,%2,%3;" : "=l"(d) : "l"(a), "l"(b), "l"(c));
    return d;
}
static __device__ __forceinline__ unsigned long long add2(unsigned long long a,
                                                          unsigned long long b) {
    unsigned long long d;
    asm("add.rn.f32x2 %0,%1,%2;" : "=l"(d) : "l"(a), "l"(b));
    return d;
}

// ---------------- K0: bit-pack adjacency ----------------
__global__ void k_pack(const int* __restrict__ adj) {
    int idx = blockIdx.x * 256 + threadIdx.x;
    unsigned m = __ballot_sync(0xffffffffu, adj[idx] > 0);
    if ((threadIdx.x & 31) == 0) g_bits[idx >> 5] = m;
}

// ---------------- probe: shifts the ncu capture slot onto k_store ----------------
__global__ void k_probe() {}

// ---------------- K1: layer-1 projection + tanh + exp tables ----------------
// grid (8, 2, 32), block 512; warp-per-node, lane owns output pair
__global__ void __launch_bounds__(512) k_proj1(
    const float* __restrict__ features, const float* __restrict__ line_emb,
    const int*   __restrict__ v_types,  const float* __restrict__ w1,
    const float* __restrict__ a_src1,   const float* __restrict__ a_dst1)
{
    extern __shared__ float sm1[];
    float* ws   = sm1;             // 12288: [t][f][l64]
    float* xv   = ws + 12288;      // 4096: 64 nodes x 64
    float* asr  = xv + 4096;       // 64
    float* ads  = asr + 64;        // 64
    int*   vt   = (int*)(ads + 64);// 64
    int tid = threadIdx.x;
    int bx = blockIdx.x, hh = blockIdx.y, b = blockIdx.z;
    int nbase = bx * 64;

    for (int i = tid; i < 12288; i += 512) {
        int l64 = i & 63, f = (i >> 6) & 63, t = i >> 12;
        int h = hh * 4 + (l64 >> 4), o = l64 & 15;
        ws[i] = w1[((t * 8 + h) * 64 + f) * 16 + o];
    }
    for (int i = tid; i < 4096; i += 512) {
        int node = i >> 6, f = i & 63;
        int n = nbase + node;
        xv[i] = (f < 32) ? features[(b * NNODE + n) * 32 + f]
                         : line_emb[(b * NNODE + n) * 32 + f - 32];
    }
    if (tid < 64) {
        int h = hh * 4 + (tid >> 4), o = tid & 15;
        asr[tid] = a_src1[h * 16 + o];
        ads[tid] = a_dst1[h * 16 + o];
        vt[tid] = v_types[b * NNODE + nbase + tid];
    }
    __syncthreads();

    int lane = tid & 31, w = tid >> 5;
    int gh = hh * 4 + (lane >> 3);
    float a0v = asr[2 * lane], a1v = asr[2 * lane + 1];
    float d0v = ads[2 * lane], d1v = ads[2 * lane + 1];
    unsigned long long z = pk2(0.f, 0.f);

    #pragma unroll
    for (int r = 0; r < 4; r++) {
        int nloc = w * 4 + r;
        int n = nbase + nloc;
        int ty = vt[nloc];
        const float* wp = ws + ty * 4096 + 2 * lane;
        const float* xp = xv + nloc * 64;
        unsigned long long acc0 = z, acc1 = z;
        #pragma unroll
        for (int f = 0; f < 64; f += 2) {
            float2 x2 = *(const float2*)&xp[f];
            unsigned long long w0 = *(const unsigned long long*)&wp[f * 64];
            unsigned long long w1v = *(const unsigned long long*)&wp[(f + 1) * 64];
            acc0 = fma2(pk2(x2.x, x2.x), w0, acc0);
            acc1 = fma2(pk2(x2.y, x2.y), w1v, acc1);
        }
        float v0, v1;
        upk2(add2(acc0, acc1), v0, v1);
        int o = (2 * lane) & 15;
        *(float2*)&g_hp1[((b * NHEAD + gh) * NNODE + n) * FHID + o] =
            make_float2(v0, v1);
        float th0 = tanhf(v0), th1 = tanhf(v1);
        float ps = th0 * a0v + th1 * a1v;
        float pd = th0 * d0v + th1 * d1v;
        #pragma unroll
        for (int off = 4; off; off >>= 1) {
            ps += __shfl_xor_sync(0xffffffffu, ps, off);
            pd += __shfl_xor_sync(0xffffffffu, pd, off);
        }
        if ((lane & 7) == 0) {
            int ai = (b * NHEAD + gh) * NNODE + n;
            g_as[ai] = ps; g_Es[ai] = expf(ps); g_Fs[ai] = expf(0.2f * ps);
            g_ad[ai] = pd; g_Ed[ai] = expf(pd); g_Fd[ai] = expf(0.2f * pd);
        }
    }
}

// ---------------- K2a: attn numerators + row sums + COALESCED attn1 store ----------------
// grid (2, 8, 32) = (nhalf, h, b), 256 threads = 8 warps, warp-per-row (32 rows each).
__global__ void __launch_bounds__(256) k_store(float* __restrict__ attn_out) {
    __shared__ float4   rc_s[256];        // (as, Es, Fs, 0) for block's rows
    __shared__ float4   tbl_s[512];       // (ad, Ed, Fd, 0) all columns
    __shared__ unsigned bits_s[256 * 16]; // [row][w]
    int tid = threadIdx.x;
    int nh = blockIdx.x, h = blockIdx.y, b = blockIdx.z;
    int bh = b * NHEAD + h;
    int n0 = nh * 256;

    for (int i = tid; i < 256; i += 256)
        rc_s[i] = make_float4(g_as[bh * 512 + n0 + i], g_Es[bh * 512 + n0 + i],
                              g_Fs[bh * 512 + n0 + i], 0.f);
    for (int i = tid; i < 512; i += 256)
        tbl_s[i] = make_float4(g_ad[bh * 512 + i], g_Ed[bh * 512 + i],
                               g_Fd[bh * 512 + i], 0.f);
    for (int i = tid; i < 4096; i += 256)
        bits_s[i] = g_bits[b * 8192 + n0 * 16 + i];
    __syncthreads();

    int lane = tid & 31, w = tid >> 5;
    float ad[16], Ed[16], Fd[16];
    #pragma unroll
    for (int k = 0; k < 4; k++)
        #pragma unroll
        for (int c = 0; c < 4; c++) {
            float4 t = tbl_s[4 * lane + c + 128 * k];
            ad[4 * k + c] = t.x; Ed[4 * k + c] = t.y; Fd[4 * k + c] = t.z;
        }
    unsigned mask[4];
    #pragma unroll
    for (int c = 0; c < 4; c++) mask[c] = 1u << (((lane & 7) * 4) + c);
    int wbase = lane >> 3;

    float* obase = attn_out + (size_t)bh * 512 * 512;
    for (int r = 0; r < 32; r++) {
        int lrow = w * 32 + r;
        int grow = n0 + lrow;
        float4 rc = rc_s[lrow];
        float nb[16];
        float sum = 0.f;
        #pragma unroll
        for (int k = 0; k < 4; k++) {
            unsigned wa = bits_s[lrow * 16 + wbase + 4 * k];
            #pragma unroll
            for (int c = 0; c < 4; c++) {
                int i = 4 * k + c;
                float sa = rc.x + ad[i];
                float t  = (sa >= 0.f) ? Ed[i] : Fd[i];
                float cc = (sa >= 0.f) ? rc.y : rc.z;
                float n  = (wa & mask[c]) ? t * cc : 0.f;
                nb[i] = n;
                sum += n;
            }
        }
        #pragma unroll
        for (int off = 16; off; off >>= 1)
            sum += __shfl_xor_sync(0xffffffffu, sum, off);
        float inva = 1.f / sum;
        if (lane == 0) g_inv[bh * 512 + grow] = inva;
        float* rp = obase + (size_t)grow * 512 + 4 * lane;
        #pragma unroll
        for (int k = 0; k < 4; k++)
            __stcs((float4*)(rp + 128 * k),
                   make_float4(nb[4*k] * inva, nb[4*k+1] * inva,
                               nb[4*k+2] * inva, nb[4*k+3] * inva));
    }
}

// ---------------- K2b: out1 GEMM, 2 rows/thread (R14 proven config) ----------------
// grid (8, 32) = (h, b), 256 threads, rows 2t/2t+1; dyn smem 73792 B
__global__ void __launch_bounds__(256, 3) k_gemm(const float* __restrict__ b1) {
    extern __shared__ float smf[];
    float*    hp_s   = smf;                       // 8192 floats [m][o]
    float4*   tbl    = (float4*)(smf + 8192);     // 512 float4 (ad, Ed, Fd, 0)
    unsigned* bits_s = (unsigned*)(smf + 10240);  // 8192 words, layout [w][r], 512 rows
    float*    b1s    = smf + 18432;               // 16
    int tid = threadIdx.x;
    int h = blockIdx.x, b = blockIdx.y;
    int bh = b * NHEAD + h;

    for (int i = tid; i < 8192; i += 256) hp_s[i] = g_hp1[bh * 8192 + i];
    for (int i = tid; i < 512; i += 256)
        tbl[i] = make_float4(g_ad[bh * 512 + i], g_Ed[bh * 512 + i],
                             g_Fd[bh * 512 + i], 0.f);
    for (int i = tid; i < 8192; i += 256) {
        int w = i >> 9, r = i & 511;
        bits_s[i] = g_bits[b * 8192 + r * 16 + w];
    }
    if (tid < 16) b1s[tid] = b1[tid];

    int na = 2 * tid, nb = na + 1;
    float as_a = g_as[bh * 512 + na], as_b = g_as[bh * 512 + nb];
    float iva = g_inv[bh * 512 + na], ivb = g_inv[bh * 512 + nb];
    float Esa = g_Es[bh * 512 + na] * iva, Fsa = g_Fs[bh * 512 + na] * iva;
    float Esb = g_Es[bh * 512 + nb] * ivb, Fsb = g_Fs[bh * 512 + nb] * ivb;
    __syncthreads();

    unsigned long long acc[16];
    unsigned long long z = pk2(0.f, 0.f);
    #pragma unroll
    for (int q = 0; q < 16; q++) acc[q] = z;

    for (int mw = 0; mw < 16; mw++) {
        unsigned wa = bits_s[mw * 512 + na];
        unsigned wb = bits_s[mw * 512 + nb];
        #pragma unroll
        for (int mi = 0; mi < 32; mi++) {
            int m = mw * 32 + mi;
            float4 t = tbl[m];
            float sa = as_a + t.x, sb = as_b + t.x;
            float ca = (sa >= 0.f) ? Esa : Fsa;
            float cb = (sb >= 0.f) ? Esb : Fsb;
            if (!((wa >> mi) & 1u)) ca = 0.f;
            if (!((wb >> mi) & 1u)) cb = 0.f;
            float ea = ca * ((sa >= 0.f) ? t.y : t.z);
            float eb = cb * ((sb >= 0.f) ? t.y : t.z);
            unsigned long long pa = pk2(ea, ea);
            unsigned long long pb = pk2(eb, eb);
            const unsigned long long* hq =
                (const unsigned long long*)(hp_s + m * 16);
            #pragma unroll
            for (int q = 0; q < 8; q++) {
                acc[q]     = fma2(pa, hq[q], acc[q]);
                acc[8 + q] = fma2(pb, hq[q], acc[8 + q]);
            }
        }
    }

    float va[16], vb[16];
    #pragma unroll
    for (int q = 0; q < 8; q++) {
        upk2(acc[q],     va[2 * q], va[2 * q + 1]);
        upk2(acc[8 + q], vb[2 * q], vb[2 * q + 1]);
    }
    float ra[16], rb[16];
    #pragma unroll
    for (int k = 0; k < 16; k++) {
        float xa = va[k] + b1s[k];
        float xb = vb[k] + b1s[k];
        ra[k] = xa > 0.f ? xa : expm1f(xa);
        rb[k] = xb > 0.f ? xb : expm1f(xb);
    }
    float* da = &g_x[(size_t)(b * 512 + na) * 128 + h * 16];
    float* db = &g_x[(size_t)(b * 512 + nb) * 128 + h * 16];
    #pragma unroll
    for (int q = 0; q < 4; q++) {
        ((float4*)da)[q] = make_float4(ra[4*q], ra[4*q+1], ra[4*q+2], ra[4*q+3]);
        ((float4*)db)[q] = make_float4(rb[4*q], rb[4*q+1], rb[4*q+2], rb[4*q+3]);
    }
}

// ---------------- K3: layer-2 projection; LDG.128 weights, quad-per-lane ----------------
__global__ void __launch_bounds__(256, 2) k_proj2(
    const int* __restrict__ v_types, const float* __restrict__ w2,
    const float* __restrict__ a_src2, const float* __restrict__ a_dst2)
{
    __shared__ float xv[32 * 128];
    __shared__ float asw[64], adw[64];
    __shared__ int   vt[32];
    int tid = threadIdx.x, b = blockIdx.y, bx = blockIdx.x;
    int nbase = bx * 32;

    for (int i = tid; i < 4096; i += 256)
        xv[i] = g_x[(size_t)(b * 512 + nbase) * 128 + i];
    if (tid < 64) { asw[tid] = a_src2[tid]; adw[tid] = a_dst2[tid]; }
    if (tid < 32) vt[tid] = v_types[b * 512 + nbase + tid];
    __syncthreads();

    int lane = tid & 31, w = tid >> 5;
    int half = lane >> 4, l16 = lane & 15;
    int o = l16 * 4;
    float a0v = asw[o], a1v = asw[o + 1], a2v = asw[o + 2], a3v = asw[o + 3];
    float d0v = adw[o], d1v = adw[o + 1], d2v = adw[o + 2], d3v = adw[o + 3];
    unsigned long long z = pk2(0.f, 0.f);

    #pragma unroll
    for (int pass = 0; pass < 2; pass++) {
        int nloc = pass * 16 + w * 2 + half;
        int n = nbase + nloc;
        int ty = vt[nloc];
        const float4* wp = (const float4*)(w2 + ty * 8192 + o);
        const float* xp = xv + nloc * 128;
        unsigned long long acc01 = z, acc23 = z;
        #pragma unroll
        for (int c = 0; c < 16; c++) {
            float4 wb[8];
            #pragma unroll
            for (int j = 0; j < 8; j++)
                wb[j] = __ldg(wp + (c * 8 + j) * 16);
            float4 xa = *(const float4*)&xp[c * 8];
            float4 xc = *(const float4*)&xp[c * 8 + 4];
            float xs[8] = {xa.x, xa.y, xa.z, xa.w, xc.x, xc.y, xc.z, xc.w};
            #pragma unroll
            for (int j = 0; j < 8; j++) {
                unsigned long long xx = pk2(xs[j], xs[j]);
                acc01 = fma2(xx, pk2(wb[j].x, wb[j].y), acc01);
                acc23 = fma2(xx, pk2(wb[j].z, wb[j].w), acc23);
            }
        }
        float v0, v1, v2, v3;
        upk2(acc01, v0, v1);
        upk2(acc23, v2, v3);
        *(float4*)&g_hp2[(size_t)(b * 512 + n) * 64 + o] =
            make_float4(v0, v1, v2, v3);
        float th0 = tanhf(v0), th1 = tanhf(v1), th2 = tanhf(v2), th3 = tanhf(v3);
        float ps = th0 * a0v + th1 * a1v + th2 * a2v + th3 * a3v;
        float pd = th0 * d0v + th1 * d1v + th2 * d2v + th3 * d3v;
        #pragma unroll
        for (int off = 8; off; off >>= 1) {
            ps += __shfl_xor_sync(0xffffffffu, ps, off);
            pd += __shfl_xor_sync(0xffffffffu, pd, off);
        }
        if (l16 == 0) {
            g_as2[b * 512 + n] = ps;
            g_ad2[b * 512 + n] = pd;
        }
    }
}

// ---------------- K4: layer-2 rows 0/1 + MLP + log_softmax ----------------
__global__ void __launch_bounds__(512) k_final(
    const float* __restrict__ b2,
    const float* __restrict__ fc1_w, const float* __restrict__ fc1_b,
    const float* __restrict__ fc2_w, const float* __restrict__ fc2_b,
    const float* __restrict__ fc3_w, const float* __restrict__ fc3_b,
    float* __restrict__ out_scores, float* __restrict__ out_vsm)
{
    __shared__ float att2[2 * 512];
    __shared__ float inv[2];
    __shared__ float part[512];
    __shared__ float xrow[128];
    __shared__ float vsm[64], v1[192], v2s[64];
    __shared__ float red[32];
    __shared__ float sc[2];
    int tid = threadIdx.x, b = blockIdx.x;
    int lane = tid & 31, wid = tid >> 5;

    float ad2 = g_ad2[b * 512 + tid];
    unsigned wrd  = g_bits[b * 8192 + (tid >> 5)];
    unsigned wrd1 = g_bits[b * 8192 + 16 + (tid >> 5)];
    float as0 = g_as2[b * 512 + 0], as1 = g_as2[b * 512 + 1];
    float s0 = as0 + ad2, s1 = as1 + ad2;
    float e0 = ((wrd  >> lane) & 1u) ? expf(s0 >= 0.f ? s0 : 0.2f * s0) : 0.f;
    float e1 = ((wrd1 >> lane) & 1u) ? expf(s1 >= 0.f ? s1 : 0.2f * s1) : 0.f;
    att2[tid] = e0;
    att2[512 + tid] = e1;
    float p0 = e0, p1 = e1;
    #pragma unroll
    for (int off = 16; off; off >>= 1) {
        p0 += __shfl_xor_sync(0xffffffffu, p0, off);
        p1 += __shfl_xor_sync(0xffffffffu, p1, off);
    }
    if (lane == 0) { red[wid] = p0; red[16 + wid] = p1; }
    __syncthreads();
    if (tid < 32) {
        float v = red[tid];
        #pragma unroll
        for (int off = 8; off; off >>= 1)
            v += __shfl_xor_sync(0xffffffffu, v, off);
        if (tid == 0)  inv[0] = 1.f / v;
        if (tid == 16) inv[1] = 1.f / v;
    }
    __syncthreads();

    {
        int r = tid >> 8, o = tid & 63, sub = (tid >> 6) & 3;
        const float* hp = g_hp2 + (size_t)b * 32768 + o;
        const float* av = att2 + r * 512 + sub * 128;
        float a0 = 0.f, a1 = 0.f, a2 = 0.f, a3 = 0.f;
        int mb = sub * 128;
        #pragma unroll 4
        for (int k = 0; k < 128; k += 4) {
            a0 = fmaf(av[k],     hp[(size_t)(mb + k) * 64],     a0);
            a1 = fmaf(av[k + 1], hp[(size_t)(mb + k + 1) * 64], a1);
            a2 = fmaf(av[k + 2], hp[(size_t)(mb + k + 2) * 64], a2);
            a3 = fmaf(av[k + 3], hp[(size_t)(mb + k + 3) * 64], a3);
        }
        part[tid] = (a0 + a1) + (a2 + a3);
    }
    __syncthreads();
    if (tid < 128) {
        int r = tid >> 6, o = tid & 63;
        float x = (part[r * 256 + o] + part[r * 256 + 64 + o] +
                   part[r * 256 + 128 + o] + part[r * 256 + 192 + o]) * inv[r] + b2[o];
        xrow[tid] = x > 0.f ? x : expm1f(x);
    }
    __syncthreads();
    if (tid < 64) {
        float vv = xrow[tid] * xrow[64 + tid];
        vsm[tid] = vv;
        out_vsm[b * 64 + tid] = vv;
    }
    __syncthreads();
    if (tid < 192) {
        float acc = fc1_b[tid];
        for (int f = 0; f < 64; f++) acc = fmaf(vsm[f], fc1_w[f * 192 + tid], acc);
        v1[tid] = fmaxf(acc, 0.f);
    }
    __syncthreads();
    if (tid < 64) {
        float acc = fc2_b[tid];
        for (int f = 0; f < 192; f++) acc = fmaf(v1[f], fc2_w[f * 64 + tid], acc);
        v2s[tid] = fmaxf(acc, 0.f);
    }
    __syncthreads();
    if (tid < 2) {
        float acc = fc3_b[tid];
        for (int f = 0; f < 64; f++) acc = fmaf(v2s[f], fc3_w[f * 2 + tid], acc);
        sc[tid] = acc;
    }
    __syncthreads();
    if (tid < 2) {
        float m = fmaxf(sc[0], sc[1]);
        float lse = m + logf(expf(sc[0] - m) + expf(sc[1] - m));
        out_scores[b * 2 + tid] = sc[tid] - lse;
    }
}

// ---------------- launch ----------------
extern "C" void kernel_launch(void* const* d_in, const int* in_sizes, int n_in,
                              void* d_out, int out_size) {
    (void)in_sizes; (void)n_in; (void)out_size;
    const float* features = (const float*)d_in[0];
    const int*   adj      = (const int*)  d_in[1];
    const float* line_emb = (const float*)d_in[5];
    const int*   v_types  = (const int*)  d_in[6];
    const float* w1       = (const float*)d_in[7];
    const float* a_src1   = (const float*)d_in[8];
    const float* a_dst1   = (const float*)d_in[9];
    const float* b1       = (const float*)d_in[10];
    const float* w2       = (const float*)d_in[11];
    const float* a_src2   = (const float*)d_in[12];
    const float* a_dst2   = (const float*)d_in[13];
    const float* b2       = (const float*)d_in[14];
    const float* fc1_w    = (const float*)d_in[15];
    const float* fc1_b    = (const float*)d_in[16];
    const float* fc2_w    = (const float*)d_in[17];
    const float* fc2_b    = (const float*)d_in[18];
    const float* fc3_w    = (const float*)d_in[19];
    const float* fc3_b    = (const float*)d_in[20];

    float* out   = (float*)d_out;
    float* vsm   = out + 64;       // v_sim_mul [32,64]
    float* attn1 = out + 2112;     // attn1 [32,8,512,512]

    cudaFuncSetAttribute(k_proj1, cudaFuncAttributeMaxDynamicSharedMemorySize, 67000);
    cudaFuncSetAttribute(k_gemm,  cudaFuncAttributeMaxDynamicSharedMemorySize, 74000);

    k_pack <<<32768, 256>>>(adj);
    k_proj1<<<dim3(8, 2, 32), 512, 66304>>>(features, line_emb, v_types, w1, a_src1, a_dst1);
    k_probe<<<1, 32>>>();
    k_store<<<dim3(2, 8, 32), 256>>>(attn1);
    k_gemm <<<dim3(8, 32), 256, 73792>>>(b1);
    k_proj2<<<dim3(16, 32), 256>>>(v_types, w2, a_src2, a_dst2);
    k_final<<<32, 512>>>(b2, fc1_w, fc1_b, fc2_w, fc2_b, fc3_w, fc3_b, out, vsm);
}